// round 11
// baseline (speedup 1.0000x reference)
#include <cuda_runtime.h>
#include <cuda_fp16.h>
#include <cstdint>

#define S_TOT  4096
#define A_TOT  1024
#define D_IN   5
#define H      64
#define M_TILE 128
#define NTHR   128
#define TILES  8
#define SPT    (M_TILE * TILES)   // structs per CTA

// ---------------- helpers ----------------
__device__ __forceinline__ uint32_t smem_u32(const void* p) {
    uint32_t a;
    asm("{ .reg .u64 t; cvta.to.shared.u64 t, %1; cvt.u32.u64 %0, t; }" : "=r"(a) : "l"(p));
    return a;
}
__device__ __forceinline__ float ex2f(float x) {
    float y; asm("ex2.approx.ftz.f32 %0, %1;" : "=f"(y) : "f"(x)); return y;
}
__device__ __forceinline__ float rcpf(float x) {
    float y; asm("rcp.approx.ftz.f32 %0, %1;" : "=f"(y) : "f"(x)); return y;
}
__device__ __forceinline__ float tanh_approx(float x) {
    float y; asm("tanh.approx.f32 %0, %1;" : "=f"(y) : "f"(x)); return y;
}
// Two accurate tanh sharing one reciprocal; only upper clamp needed.
__device__ __forceinline__ float2 tanh2(float a, float b) {
    const float c = 2.885390081777927f;                 // 2*log2(e)
    a = fminf(a, 9.0f);
    b = fminf(b, 9.0f);
    float pa = ex2f(a * c) + 1.0f;
    float pb = ex2f(b * c) + 1.0f;
    float r2 = 2.0f * rcpf(pa * pb);
    return make_float2(1.0f - r2 * pb, 1.0f - r2 * pa);
}
__device__ __forceinline__ void split_pack_h(float x, float y, uint32_t& hi, uint32_t& lo) {
    __half2 h2 = __floats2half2_rn(x, y);
    float hx = __low2float(h2), hy = __high2float(h2);
    __half2 l2 = __floats2half2_rn(x - hx, y - hy);
    hi = *reinterpret_cast<uint32_t*>(&h2);
    lo = *reinterpret_cast<uint32_t*>(&l2);
}
__device__ __forceinline__ void ldsm_x4t(uint32_t* r, uint32_t addr) {
    asm volatile("ldmatrix.sync.aligned.m8n8.x4.trans.shared.b16 {%0,%1,%2,%3}, [%4];"
                 : "=r"(r[0]), "=r"(r[1]), "=r"(r[2]), "=r"(r[3]) : "r"(addr));
}
__device__ __forceinline__ void mma_f16_k16(float* c, const uint32_t* a, const uint32_t* b) {
    asm volatile("mma.sync.aligned.m16n8k16.row.col.f32.f16.f16.f32 "
                 "{%0,%1,%2,%3}, {%4,%5,%6,%7}, {%8,%9}, {%0,%1,%2,%3};"
                 : "+f"(c[0]), "+f"(c[1]), "+f"(c[2]), "+f"(c[3])
                 : "r"(a[0]), "r"(a[1]), "r"(a[2]), "r"(a[3]), "r"(b[0]), "r"(b[1]));
}
__device__ __forceinline__ void mma_f16_k8(float* c, const uint32_t* a, uint32_t b) {
    asm volatile("mma.sync.aligned.m16n8k8.row.col.f32.f16.f16.f32 "
                 "{%0,%1,%2,%3}, {%4,%5}, {%6}, {%0,%1,%2,%3};"
                 : "+f"(c[0]), "+f"(c[1]), "+f"(c[2]), "+f"(c[3])
                 : "r"(a[0]), "r"(a[1]), "r"(b));
}
__device__ __forceinline__ void cp_async4(uint32_t dst, const float* src) {
    asm volatile("cp.async.ca.shared.global [%0], [%1], 4;" :: "r"(dst), "l"(src));
}
#define CP_COMMIT() asm volatile("cp.async.commit_group;" ::: "memory")
#define CP_WAIT0()  asm volatile("cp.async.wait_group 0;" ::: "memory")

// Static smem (~27.5 KB). B tiles: rows 128B, 16B chunks XOR-swizzled (chunk ^= row&7).
struct SmemT {
    __align__(128) __half Bhi[H * H];          // 8 KB  W2 hi [k][n]
    __align__(128) __half Blo[H * H];          // 8 KB  W2 lo
    __align__(16)  float  G[2][M_TILE][8];     // 8 KB  g fp32, k padded 5->8, dbl-buffer
    __align__(16)  float  W1s[H][8];           // 2 KB  W1 fp32 [n][k], k padded
    float b1s[H], b2s[H], w3s[H], b3s;
};

__global__ __launch_bounds__(NTHR, 5) void mlp_kernel(
    const float* __restrict__ g,  const float* __restrict__ W1, const float* __restrict__ b1,
    const float* __restrict__ W2, const float* __restrict__ b2,
    const float* __restrict__ W3, const float* __restrict__ b3, float* __restrict__ out)
{
    __shared__ SmemT sm;
    const int tid  = threadIdx.x;
    const int wid  = tid >> 5;
    const int lane = tid & 31;
    const int a    = blockIdx.y;
    const int sBase = blockIdx.x * SPT;
    const size_t rstride = (size_t)A_TOT * D_IN;

    // per-thread g-staging coords (reused every tile)
    const int ge   = tid;                      // pattern repeats with p
    // zero G pads (cols 5..7) once; cp.async never touches them
    sm.G[0][tid][5] = 0.f; sm.G[0][tid][6] = 0.f; sm.G[0][tid][7] = 0.f;
    sm.G[1][tid][5] = 0.f; sm.G[1][tid][6] = 0.f; sm.G[1][tid][7] = 0.f;

    // ---- kick off async g load for tile 0 ----
    {
        const float* gp = g + ((size_t)sBase * A_TOT + a) * D_IN;
        #pragma unroll
        for (int p = 0; p < 5; p++) {
            int e = p * NTHR + ge;
            int row = e / 5, d = e - row * 5;
            cp_async4(smem_u32(&sm.G[0][row][d]), gp + (size_t)row * rstride + d);
        }
        CP_COMMIT();
    }

    // ---- once-per-CTA staging ----
    if (tid < H) {
        sm.b1s[tid] = b1[(size_t)a * H + tid];
        sm.b2s[tid] = b2[(size_t)a * H + tid];
        sm.w3s[tid] = W3[(size_t)a * H + tid];
    }
    if (tid == 0) sm.b3s = b3[a];

    {   // W2 -> Bhi/Blo, fp16 hi/lo, swizzled
        const float* W2a = W2 + (size_t)a * H * H;
        #pragma unroll
        for (int it = 0; it < 4; it++) {
            int ch = tid + it * NTHR;
            int k = ch >> 3, nc = ch & 7;
            const float4* src = (const float4*)(W2a + k * H + nc * 8);
            float4 w0 = src[0], w1 = src[1];
            uint32_t hi[4], lo[4];
            split_pack_h(w0.x, w0.y, hi[0], lo[0]);
            split_pack_h(w0.z, w0.w, hi[1], lo[1]);
            split_pack_h(w1.x, w1.y, hi[2], lo[2]);
            split_pack_h(w1.z, w1.w, hi[3], lo[3]);
            uint32_t off = (uint32_t)k * 128 + ((uint32_t)(nc ^ (k & 7)) << 4);
            *(uint4*)((char*)sm.Bhi + off) = make_uint4(hi[0], hi[1], hi[2], hi[3]);
            *(uint4*)((char*)sm.Blo + off) = make_uint4(lo[0], lo[1], lo[2], lo[3]);
        }
    }
    {   // W1 fp32 transposed [n][k], k padded with zeros
        const float* W1a = W1 + (size_t)a * D_IN * H;
        #pragma unroll
        for (int it = 0; it < 4; it++) {
            int e = it * NTHR + tid;                     // e = n*8 + k
            int n = e >> 3, k = e & 7;
            sm.W1s[n][k] = (k < D_IN) ? W1a[k * H + n] : 0.0f;
        }
    }
    CP_WAIT0();
    __syncthreads();

    // ---- W1 fragments (built once, held in regs) ----
    uint32_t w1h[8], w1l[8];
    {
        int q = lane >> 2, k0 = (lane & 3) * 2;
        #pragma unroll
        for (int nt = 0; nt < 8; nt++) {
            float2 v = *(const float2*)&sm.W1s[nt * 8 + q][k0];
            split_pack_h(v.x, v.y, w1h[nt], w1l[nt]);
        }
    }

    const int c2i = (lane & 3) * 2;
    // x4t lane addressing (lane-consts)
    const int r_in  = lane & 7;
    const int sel_k = (lane >> 3) & 1;
    const int sel_n = lane >> 4;

    for (int t = 0; t < TILES; t++) {
        const int buf = t & 1;

        // ---- async prefetch of next g tile ----
        if (t + 1 < TILES) {
            const float* gp = g + ((size_t)(sBase + (t + 1) * M_TILE) * A_TOT + a) * D_IN;
            #pragma unroll
            for (int p = 0; p < 5; p++) {
                int e = p * NTHR + ge;
                int row = e / 5, d = e - row * 5;
                cp_async4(smem_u32(&sm.G[1 - buf][row][d]), gp + (size_t)row * rstride + d);
            }
            CP_COMMIT();
        }

        // ---- G fragments: direct build from fp32 smem (conflict-free LDS.64) ----
        uint32_t gfh[2][2], gfl[2][2];
        {
            int rbase = wid * 32 + (lane >> 2);
            #pragma unroll
            for (int rt = 0; rt < 2; rt++)
                #pragma unroll
                for (int hh = 0; hh < 2; hh++) {
                    int row = rbase + rt * 16 + hh * 8;
                    float2 v = *(const float2*)&sm.G[buf][row][c2i];
                    split_pack_h(v.x, v.y, gfh[rt][hh], gfl[rt][hh]);
                }
        }

        // ---- layer 1: C1 = b1 + Ghi*W1hi (k8) + [Ghi|Glo]*[W1lo|W1hi] (k16) ----
        uint32_t Af[2][4][4];
        #pragma unroll
        for (int nt = 0; nt < 8; nt++) {
            float2 bb = *(const float2*)&sm.b1s[nt * 8 + c2i];
            #pragma unroll
            for (int rt = 0; rt < 2; rt++) {
                float C1[4] = {bb.x, bb.y, bb.x, bb.y};
                mma_f16_k8(C1, gfh[rt], w1h[nt]);
                uint32_t ak16[4] = {gfh[rt][0], gfh[rt][1], gfl[rt][0], gfl[rt][1]};
                uint32_t bk16[2] = {w1l[nt], w1h[nt]};
                mma_f16_k16(C1, ak16, bk16);
                float2 tt = tanh2(C1[0], C1[1]);
                float2 uu = tanh2(C1[2], C1[3]);
                __half2 th = __floats2half2_rn(tt.x, tt.y);
                __half2 uh = __floats2half2_rn(uu.x, uu.y);
                Af[rt][nt >> 1][(nt & 1) * 2 + 0] = *reinterpret_cast<uint32_t*>(&th);
                Af[rt][nt >> 1][(nt & 1) * 2 + 1] = *reinterpret_cast<uint32_t*>(&uh);
            }
        }

        // ---- layer 2 + fused epilogue ----
        float ee[4] = {0.f, 0.f, 0.f, 0.f};
        #pragma unroll
        for (int nh = 0; nh < 2; nh++) {
            float C[2][4][4];
            #pragma unroll
            for (int nt = 0; nt < 4; nt++) {
                float2 bb = *(const float2*)&sm.b2s[(nh * 4 + nt) * 8 + c2i];
                #pragma unroll
                for (int rt = 0; rt < 2; rt++) {
                    C[rt][nt][0] = bb.x; C[rt][nt][1] = bb.y;
                    C[rt][nt][2] = bb.x; C[rt][nt][3] = bb.y;
                }
            }
            #pragma unroll
            for (int ks = 0; ks < 4; ks++) {
                #pragma unroll
                for (int ntp = 0; ntp < 2; ntp++) {
                    int row = ks * 16 + sel_k * 8 + r_in;
                    int ntc = nh * 4 + ntp * 2 + sel_n;
                    uint32_t off = (uint32_t)row * 128 + ((uint32_t)(ntc ^ r_in) << 4);
                    uint32_t bh[4], bl[4];
                    ldsm_x4t(bh, smem_u32((char*)sm.Bhi + off));
                    ldsm_x4t(bl, smem_u32((char*)sm.Blo + off));
                    #pragma unroll
                    for (int ntl = 0; ntl < 2; ntl++) {
                        int nt = ntp * 2 + ntl;
                        #pragma unroll
                        for (int rt = 0; rt < 2; rt++) {
                            mma_f16_k16(C[rt][nt], Af[rt][ks], &bh[ntl * 2]);
                            mma_f16_k16(C[rt][nt], Af[rt][ks], &bl[ntl * 2]);
                        }
                    }
                }
            }
            #pragma unroll
            for (int nt = 0; nt < 4; nt++) {
                float2 ww = *(const float2*)&sm.w3s[(nh * 4 + nt) * 8 + c2i];
                #pragma unroll
                for (int rt = 0; rt < 2; rt++) {
                    float t0 = tanh_approx(C[rt][nt][0]);
                    float t1 = tanh_approx(C[rt][nt][1]);
                    float t2 = tanh_approx(C[rt][nt][2]);
                    float t3 = tanh_approx(C[rt][nt][3]);
                    ee[rt * 2 + 0] = fmaf(t0, ww.x, fmaf(t1, ww.y, ee[rt * 2 + 0]));
                    ee[rt * 2 + 1] = fmaf(t2, ww.x, fmaf(t3, ww.y, ee[rt * 2 + 1]));
                }
            }
        }

        // ---- reduce + store ----
        #pragma unroll
        for (int i = 0; i < 4; i++) {
            ee[i] += __shfl_xor_sync(0xFFFFFFFFu, ee[i], 1);
            ee[i] += __shfl_xor_sync(0xFFFFFFFFu, ee[i], 2);
        }
        if ((lane & 3) == 0) {
            float e3 = sm.b3s;
            int q = lane >> 2;
            int r = sBase + t * M_TILE + wid * 32 + q;
            out[(size_t)(r)      * A_TOT + a] = ee[0] + e3;
            out[(size_t)(r + 8)  * A_TOT + a] = ee[1] + e3;
            out[(size_t)(r + 16) * A_TOT + a] = ee[2] + e3;
            out[(size_t)(r + 24) * A_TOT + a] = ee[3] + e3;
        }

        // ---- wait for prefetched g, single barrier per tile ----
        if (t + 1 < TILES) {
            CP_WAIT0();
            __syncthreads();
        }
    }
}

extern "C" void kernel_launch(void* const* d_in, const int* in_sizes, int n_in,
                              void* d_out, int out_size)
{
    const float* g  = (const float*)d_in[0];
    const float* W1 = (const float*)d_in[1];
    const float* b1 = (const float*)d_in[2];
    const float* W2 = (const float*)d_in[3];
    const float* b2 = (const float*)d_in[4];
    const float* W3 = (const float*)d_in[5];
    const float* b3 = (const float*)d_in[6];
    float* out = (float*)d_out;

    mlp_kernel<<<dim3(S_TOT / SPT, A_TOT), NTHR>>>(g, W1, b1, W2, b2, W3, b3, out);
}

// round 12
// speedup vs baseline: 1.2356x; 1.2356x over previous
#include <cuda_runtime.h>
#include <cuda_fp16.h>
#include <cstdint>

#define S_TOT  4096
#define A_TOT  1024
#define D_IN   5
#define H      64
#define M_TILE 128
#define NTHR   128
#define TILES  8
#define SPT    (M_TILE * TILES)   // structs per CTA

// ---------------- helpers ----------------
__device__ __forceinline__ uint32_t smem_u32(const void* p) {
    uint32_t a;
    asm("{ .reg .u64 t; cvta.to.shared.u64 t, %1; cvt.u32.u64 %0, t; }" : "=r"(a) : "l"(p));
    return a;
}
__device__ __forceinline__ float ex2f(float x) {
    float y; asm("ex2.approx.ftz.f32 %0, %1;" : "=f"(y) : "f"(x)); return y;
}
__device__ __forceinline__ float rcpf(float x) {
    float y; asm("rcp.approx.ftz.f32 %0, %1;" : "=f"(y) : "f"(x)); return y;
}
__device__ __forceinline__ float tanh_approx(float x) {
    float y; asm("tanh.approx.f32 %0, %1;" : "=f"(y) : "f"(x)); return y;
}
// Two accurate tanh sharing one reciprocal; only upper clamp needed.
__device__ __forceinline__ float2 tanh2(float a, float b) {
    const float c = 2.885390081777927f;                 // 2*log2(e)
    a = fminf(a, 9.0f);
    b = fminf(b, 9.0f);
    float pa = ex2f(a * c) + 1.0f;
    float pb = ex2f(b * c) + 1.0f;
    float r2 = 2.0f * rcpf(pa * pb);
    return make_float2(1.0f - r2 * pb, 1.0f - r2 * pa);
}
__device__ __forceinline__ void split_pack_h(float x, float y, uint32_t& hi, uint32_t& lo) {
    __half2 h2 = __floats2half2_rn(x, y);
    float hx = __low2float(h2), hy = __high2float(h2);
    __half2 l2 = __floats2half2_rn(x - hx, y - hy);
    hi = *reinterpret_cast<uint32_t*>(&h2);
    lo = *reinterpret_cast<uint32_t*>(&l2);
}
__device__ __forceinline__ void ldsm_x4t(uint32_t* r, uint32_t addr) {
    asm volatile("ldmatrix.sync.aligned.m8n8.x4.trans.shared.b16 {%0,%1,%2,%3}, [%4];"
                 : "=r"(r[0]), "=r"(r[1]), "=r"(r[2]), "=r"(r[3]) : "r"(addr));
}
__device__ __forceinline__ void mma_f16_k16(float* c, const uint32_t* a, const uint32_t* b) {
    asm volatile("mma.sync.aligned.m16n8k16.row.col.f32.f16.f16.f32 "
                 "{%0,%1,%2,%3}, {%4,%5,%6,%7}, {%8,%9}, {%0,%1,%2,%3};"
                 : "+f"(c[0]), "+f"(c[1]), "+f"(c[2]), "+f"(c[3])
                 : "r"(a[0]), "r"(a[1]), "r"(a[2]), "r"(a[3]), "r"(b[0]), "r"(b[1]));
}
__device__ __forceinline__ void mma_f16_k8(float* c, const uint32_t* a, uint32_t b) {
    asm volatile("mma.sync.aligned.m16n8k8.row.col.f32.f16.f16.f32 "
                 "{%0,%1,%2,%3}, {%4,%5}, {%6}, {%0,%1,%2,%3};"
                 : "+f"(c[0]), "+f"(c[1]), "+f"(c[2]), "+f"(c[3])
                 : "r"(a[0]), "r"(a[1]), "r"(b));
}
__device__ __forceinline__ void cp_async4(uint32_t dst, const float* src) {
    asm volatile("cp.async.ca.shared.global [%0], [%1], 4;" :: "r"(dst), "l"(src));
}
#define CP_COMMIT() asm volatile("cp.async.commit_group;" ::: "memory")
#define CP_WAIT0()  asm volatile("cp.async.wait_group 0;" ::: "memory")

// Static smem (~19.5 KB). B tile: rows 128B, 16B chunks XOR-swizzled (chunk ^= row&7).
struct SmemT {
    __align__(128) __half Bhi[H * H];          // 8 KB  W2 fp16 [k][n]
    __align__(16)  float  G[2][M_TILE][8];     // 8 KB  g fp32, k padded 5->8, dbl-buffer
    __align__(16)  float  W1s[H][8];           // 2 KB  W1 fp32 [n][k], k padded
    float b1s[H], b2s[H], w3s[H], b3s;
};

__global__ __launch_bounds__(NTHR, 5) void mlp_kernel(
    const float* __restrict__ g,  const float* __restrict__ W1, const float* __restrict__ b1,
    const float* __restrict__ W2, const float* __restrict__ b2,
    const float* __restrict__ W3, const float* __restrict__ b3, float* __restrict__ out)
{
    __shared__ SmemT sm;
    const int tid  = threadIdx.x;
    const int wid  = tid >> 5;
    const int lane = tid & 31;
    const int a    = blockIdx.y;
    const int sBase = blockIdx.x * SPT;
    const size_t rstride = (size_t)A_TOT * D_IN;

    // zero G pads (cols 5..7) once; cp.async never touches them
    sm.G[0][tid][5] = 0.f; sm.G[0][tid][6] = 0.f; sm.G[0][tid][7] = 0.f;
    sm.G[1][tid][5] = 0.f; sm.G[1][tid][6] = 0.f; sm.G[1][tid][7] = 0.f;

    // ---- kick off async g load for tile 0 ----
    {
        const float* gp = g + ((size_t)sBase * A_TOT + a) * D_IN;
        #pragma unroll
        for (int p = 0; p < 5; p++) {
            int e = p * NTHR + tid;
            int row = e / 5, d = e - row * 5;
            cp_async4(smem_u32(&sm.G[0][row][d]), gp + (size_t)row * rstride + d);
        }
        CP_COMMIT();
    }

    // ---- once-per-CTA staging ----
    if (tid < H) {
        sm.b1s[tid] = b1[(size_t)a * H + tid];
        sm.b2s[tid] = b2[(size_t)a * H + tid];
        sm.w3s[tid] = W3[(size_t)a * H + tid];
    }
    if (tid == 0) sm.b3s = b3[a];

    {   // W2 -> Bhi (single fp16), swizzled
        const float* W2a = W2 + (size_t)a * H * H;
        #pragma unroll
        for (int it = 0; it < 4; it++) {
            int ch = tid + it * NTHR;
            int k = ch >> 3, nc = ch & 7;
            const float4* src = (const float4*)(W2a + k * H + nc * 8);
            float4 w0 = src[0], w1 = src[1];
            __half2 h0 = __floats2half2_rn(w0.x, w0.y);
            __half2 h1 = __floats2half2_rn(w0.z, w0.w);
            __half2 h2 = __floats2half2_rn(w1.x, w1.y);
            __half2 h3 = __floats2half2_rn(w1.z, w1.w);
            uint32_t off = (uint32_t)k * 128 + ((uint32_t)(nc ^ (k & 7)) << 4);
            *(uint4*)((char*)sm.Bhi + off) = make_uint4(
                *reinterpret_cast<uint32_t*>(&h0), *reinterpret_cast<uint32_t*>(&h1),
                *reinterpret_cast<uint32_t*>(&h2), *reinterpret_cast<uint32_t*>(&h3));
        }
    }
    {   // W1 fp32 transposed [n][k], k padded with zeros
        const float* W1a = W1 + (size_t)a * D_IN * H;
        #pragma unroll
        for (int it = 0; it < 4; it++) {
            int e = it * NTHR + tid;                     // e = n*8 + k
            int n = e >> 3, k = e & 7;
            sm.W1s[n][k] = (k < D_IN) ? W1a[k * H + n] : 0.0f;
        }
    }
    CP_WAIT0();
    __syncthreads();

    // ---- W1 fragments (built once, held in regs) ----
    uint32_t w1h[8], w1l[8];
    {
        int q = lane >> 2, k0 = (lane & 3) * 2;
        #pragma unroll
        for (int nt = 0; nt < 8; nt++) {
            float2 v = *(const float2*)&sm.W1s[nt * 8 + q][k0];
            split_pack_h(v.x, v.y, w1h[nt], w1l[nt]);
        }
    }

    const int c2i = (lane & 3) * 2;
    // x4t lane addressing (lane-consts)
    const int r_in  = lane & 7;
    const int sel_k = (lane >> 3) & 1;
    const int sel_n = lane >> 4;

    for (int t = 0; t < TILES; t++) {
        const int buf = t & 1;

        // ---- async prefetch of next g tile ----
        if (t + 1 < TILES) {
            const float* gp = g + ((size_t)(sBase + (t + 1) * M_TILE) * A_TOT + a) * D_IN;
            #pragma unroll
            for (int p = 0; p < 5; p++) {
                int e = p * NTHR + tid;
                int row = e / 5, d = e - row * 5;
                cp_async4(smem_u32(&sm.G[1 - buf][row][d]), gp + (size_t)row * rstride + d);
            }
            CP_COMMIT();
        }

        // ---- G fragments: direct build from fp32 smem (conflict-free LDS.64) ----
        uint32_t gfh[2][2], gfl[2][2];
        {
            int rbase = wid * 32 + (lane >> 2);
            #pragma unroll
            for (int rt = 0; rt < 2; rt++)
                #pragma unroll
                for (int hh = 0; hh < 2; hh++) {
                    int row = rbase + rt * 16 + hh * 8;
                    float2 v = *(const float2*)&sm.G[buf][row][c2i];
                    split_pack_h(v.x, v.y, gfh[rt][hh], gfl[rt][hh]);
                }
        }

        // ---- layer 1: C1 = b1 + Ghi*W1hi (k8) + [Ghi|Glo]*[W1lo|W1hi] (k16) ----
        uint32_t Af[2][4][4];
        #pragma unroll
        for (int nt = 0; nt < 8; nt++) {
            float2 bb = *(const float2*)&sm.b1s[nt * 8 + c2i];
            #pragma unroll
            for (int rt = 0; rt < 2; rt++) {
                float C1[4] = {bb.x, bb.y, bb.x, bb.y};
                mma_f16_k8(C1, gfh[rt], w1h[nt]);
                uint32_t ak16[4] = {gfh[rt][0], gfh[rt][1], gfl[rt][0], gfl[rt][1]};
                uint32_t bk16[2] = {w1l[nt], w1h[nt]};
                mma_f16_k16(C1, ak16, bk16);
                float2 tt = tanh2(C1[0], C1[1]);
                float2 uu = tanh2(C1[2], C1[3]);
                __half2 th = __floats2half2_rn(tt.x, tt.y);
                __half2 uh = __floats2half2_rn(uu.x, uu.y);
                Af[rt][nt >> 1][(nt & 1) * 2 + 0] = *reinterpret_cast<uint32_t*>(&th);
                Af[rt][nt >> 1][(nt & 1) * 2 + 1] = *reinterpret_cast<uint32_t*>(&uh);
            }
        }

        // ---- layer 2 (single fp16 product) + fused epilogue ----
        float ee[4] = {0.f, 0.f, 0.f, 0.f};
        #pragma unroll
        for (int nh = 0; nh < 2; nh++) {
            float C[2][4][4];
            #pragma unroll
            for (int nt = 0; nt < 4; nt++) {
                float2 bb = *(const float2*)&sm.b2s[(nh * 4 + nt) * 8 + c2i];
                #pragma unroll
                for (int rt = 0; rt < 2; rt++) {
                    C[rt][nt][0] = bb.x; C[rt][nt][1] = bb.y;
                    C[rt][nt][2] = bb.x; C[rt][nt][3] = bb.y;
                }
            }
            #pragma unroll
            for (int ks = 0; ks < 4; ks++) {
                #pragma unroll
                for (int ntp = 0; ntp < 2; ntp++) {
                    int row = ks * 16 + sel_k * 8 + r_in;
                    int ntc = nh * 4 + ntp * 2 + sel_n;
                    uint32_t off = (uint32_t)row * 128 + ((uint32_t)(ntc ^ r_in) << 4);
                    uint32_t bh[4];
                    ldsm_x4t(bh, smem_u32((char*)sm.Bhi + off));
                    #pragma unroll
                    for (int ntl = 0; ntl < 2; ntl++) {
                        int nt = ntp * 2 + ntl;
                        #pragma unroll
                        for (int rt = 0; rt < 2; rt++)
                            mma_f16_k16(C[rt][nt], Af[rt][ks], &bh[ntl * 2]);
                    }
                }
            }
            #pragma unroll
            for (int nt = 0; nt < 4; nt++) {
                float2 ww = *(const float2*)&sm.w3s[(nh * 4 + nt) * 8 + c2i];
                #pragma unroll
                for (int rt = 0; rt < 2; rt++) {
                    float t0 = tanh_approx(C[rt][nt][0]);
                    float t1 = tanh_approx(C[rt][nt][1]);
                    float t2 = tanh_approx(C[rt][nt][2]);
                    float t3 = tanh_approx(C[rt][nt][3]);
                    ee[rt * 2 + 0] = fmaf(t0, ww.x, fmaf(t1, ww.y, ee[rt * 2 + 0]));
                    ee[rt * 2 + 1] = fmaf(t2, ww.x, fmaf(t3, ww.y, ee[rt * 2 + 1]));
                }
            }
        }

        // ---- reduce + store ----
        #pragma unroll
        for (int i = 0; i < 4; i++) {
            ee[i] += __shfl_xor_sync(0xFFFFFFFFu, ee[i], 1);
            ee[i] += __shfl_xor_sync(0xFFFFFFFFu, ee[i], 2);
        }
        if ((lane & 3) == 0) {
            float e3 = sm.b3s;
            int q = lane >> 2;
            int r = sBase + t * M_TILE + wid * 32 + q;
            out[(size_t)(r)      * A_TOT + a] = ee[0] + e3;
            out[(size_t)(r + 8)  * A_TOT + a] = ee[1] + e3;
            out[(size_t)(r + 16) * A_TOT + a] = ee[2] + e3;
            out[(size_t)(r + 24) * A_TOT + a] = ee[3] + e3;
        }

        // ---- wait for prefetched g, single barrier per tile ----
        if (t + 1 < TILES) {
            CP_WAIT0();
            __syncthreads();
        }
    }
}

extern "C" void kernel_launch(void* const* d_in, const int* in_sizes, int n_in,
                              void* d_out, int out_size)
{
    const float* g  = (const float*)d_in[0];
    const float* W1 = (const float*)d_in[1];
    const float* b1 = (const float*)d_in[2];
    const float* W2 = (const float*)d_in[3];
    const float* b2 = (const float*)d_in[4];
    const float* W3 = (const float*)d_in[5];
    const float* b3 = (const float*)d_in[6];
    float* out = (float*)d_out;

    mlp_kernel<<<dim3(S_TOT / SPT, A_TOT), NTHR>>>(g, W1, b1, W2, b2, W3, b3, out);
}

// round 14
// speedup vs baseline: 1.4159x; 1.1459x over previous
#include <cuda_runtime.h>
#include <cuda_fp16.h>
#include <cstdint>

#define S_TOT  4096
#define A_TOT  1024
#define D_IN   5
#define H      64
#define M_TILE 128
#define NTHR   128
#define TILES  8
#define SPT    (M_TILE * TILES)   // structs per CTA

// ---------------- helpers ----------------
__device__ __forceinline__ uint32_t smem_u32(const void* p) {
    uint32_t a;
    asm("{ .reg .u64 t; cvta.to.shared.u64 t, %1; cvt.u32.u64 %0, t; }" : "=r"(a) : "l"(p));
    return a;
}
__device__ __forceinline__ float tanh_approx(float x) {
    float y; asm("tanh.approx.f32 %0, %1;" : "=f"(y) : "f"(x)); return y;
}
__device__ __forceinline__ void split_pack_h(float x, float y, uint32_t& hi, uint32_t& lo) {
    __half2 h2 = __floats2half2_rn(x, y);
    float hx = __low2float(h2), hy = __high2float(h2);
    __half2 l2 = __floats2half2_rn(x - hx, y - hy);
    hi = *reinterpret_cast<uint32_t*>(&h2);
    lo = *reinterpret_cast<uint32_t*>(&l2);
}
__device__ __forceinline__ void ldsm_x4t(uint32_t* r, uint32_t addr) {
    asm volatile("ldmatrix.sync.aligned.m8n8.x4.trans.shared.b16 {%0,%1,%2,%3}, [%4];"
                 : "=r"(r[0]), "=r"(r[1]), "=r"(r[2]), "=r"(r[3]) : "r"(addr));
}
__device__ __forceinline__ void mma_f16_k16(float* c, const uint32_t* a, const uint32_t* b) {
    asm volatile("mma.sync.aligned.m16n8k16.row.col.f32.f16.f16.f32 "
                 "{%0,%1,%2,%3}, {%4,%5,%6,%7}, {%8,%9}, {%0,%1,%2,%3};"
                 : "+f"(c[0]), "+f"(c[1]), "+f"(c[2]), "+f"(c[3])
                 : "r"(a[0]), "r"(a[1]), "r"(a[2]), "r"(a[3]), "r"(b[0]), "r"(b[1]));
}
__device__ __forceinline__ void mma_f16_k8(float* c, const uint32_t* a, uint32_t b) {
    asm volatile("mma.sync.aligned.m16n8k8.row.col.f32.f16.f16.f32 "
                 "{%0,%1,%2,%3}, {%4,%5}, {%6}, {%0,%1,%2,%3};"
                 : "+f"(c[0]), "+f"(c[1]), "+f"(c[2]), "+f"(c[3])
                 : "r"(a[0]), "r"(a[1]), "r"(b));
}
__device__ __forceinline__ void cp_async4(uint32_t dst, const float* src) {
    asm volatile("cp.async.ca.shared.global [%0], [%1], 4;" :: "r"(dst), "l"(src));
}
#define CP_COMMIT() asm volatile("cp.async.commit_group;" ::: "memory")
#define CP_WAIT0()  asm volatile("cp.async.wait_group 0;" ::: "memory")

// Static smem (~19.5 KB). B tile: rows 128B, 16B chunks XOR-swizzled (chunk ^= row&7).
struct SmemT {
    __align__(128) __half Bhi[H * H];          // 8 KB  W2 fp16 [k][n]
    __align__(16)  float  G[2][M_TILE][8];     // 8 KB  g fp32, k padded 5->8, dbl-buffer
    __align__(16)  float  W1s[H][8];           // 2 KB  W1 fp32 [n][k], k padded
    float b1s[H], b2s[H], w3s[H], b3s;
};

__global__ __launch_bounds__(NTHR, 5) void mlp_kernel(
    const float* __restrict__ g,  const float* __restrict__ W1, const float* __restrict__ b1,
    const float* __restrict__ W2, const float* __restrict__ b2,
    const float* __restrict__ W3, const float* __restrict__ b3, float* __restrict__ out)
{
    __shared__ SmemT sm;
    const int tid  = threadIdx.x;
    const int wid  = tid >> 5;
    const int lane = tid & 31;
    const int a    = blockIdx.y;
    const int sBase = blockIdx.x * SPT;
    const size_t rstride = (size_t)A_TOT * D_IN;

    // zero G pads (cols 5..7) once; cp.async never touches them
    sm.G[0][tid][5] = 0.f; sm.G[0][tid][6] = 0.f; sm.G[0][tid][7] = 0.f;
    sm.G[1][tid][5] = 0.f; sm.G[1][tid][6] = 0.f; sm.G[1][tid][7] = 0.f;

    // ---- kick off async g load for tile 0 ----
    {
        const float* gp = g + ((size_t)sBase * A_TOT + a) * D_IN;
        #pragma unroll
        for (int p = 0; p < 5; p++) {
            int e = p * NTHR + tid;
            int row = e / 5, d = e - row * 5;
            cp_async4(smem_u32(&sm.G[0][row][d]), gp + (size_t)row * rstride + d);
        }
        CP_COMMIT();
    }

    // ---- once-per-CTA staging ----
    if (tid < H) {
        sm.b1s[tid] = b1[(size_t)a * H + tid];
        sm.b2s[tid] = b2[(size_t)a * H + tid];
        sm.w3s[tid] = W3[(size_t)a * H + tid];
    }
    if (tid == 0) sm.b3s = b3[a];

    {   // W2 -> Bhi (single fp16), swizzled
        const float* W2a = W2 + (size_t)a * H * H;
        #pragma unroll
        for (int it = 0; it < 4; it++) {
            int ch = tid + it * NTHR;
            int k = ch >> 3, nc = ch & 7;
            const float4* src = (const float4*)(W2a + k * H + nc * 8);
            float4 w0 = src[0], w1 = src[1];
            __half2 h0 = __floats2half2_rn(w0.x, w0.y);
            __half2 h1 = __floats2half2_rn(w0.z, w0.w);
            __half2 h2 = __floats2half2_rn(w1.x, w1.y);
            __half2 h3 = __floats2half2_rn(w1.z, w1.w);
            uint32_t off = (uint32_t)k * 128 + ((uint32_t)(nc ^ (k & 7)) << 4);
            *(uint4*)((char*)sm.Bhi + off) = make_uint4(
                *reinterpret_cast<uint32_t*>(&h0), *reinterpret_cast<uint32_t*>(&h1),
                *reinterpret_cast<uint32_t*>(&h2), *reinterpret_cast<uint32_t*>(&h3));
        }
    }
    {   // W1 fp32 transposed [n][k], k padded with zeros
        const float* W1a = W1 + (size_t)a * D_IN * H;
        #pragma unroll
        for (int it = 0; it < 4; it++) {
            int e = it * NTHR + tid;                     // e = n*8 + k
            int n = e >> 3, k = e & 7;
            sm.W1s[n][k] = (k < D_IN) ? W1a[k * H + n] : 0.0f;
        }
    }
    CP_WAIT0();
    __syncthreads();

    // ---- W1 fragments (built once, held in regs) ----
    uint32_t w1h[8], w1l[8];
    {
        int q = lane >> 2, k0 = (lane & 3) * 2;
        #pragma unroll
        for (int nt = 0; nt < 8; nt++) {
            float2 v = *(const float2*)&sm.W1s[nt * 8 + q][k0];
            split_pack_h(v.x, v.y, w1h[nt], w1l[nt]);
        }
    }

    const int c2i = (lane & 3) * 2;
    // x4t lane addressing (lane-consts)
    const int r_in  = lane & 7;
    const int sel_k = (lane >> 3) & 1;
    const int sel_n = lane >> 4;

    for (int t = 0; t < TILES; t++) {
        const int buf = t & 1;

        // ---- async prefetch of next g tile ----
        if (t + 1 < TILES) {
            const float* gp = g + ((size_t)(sBase + (t + 1) * M_TILE) * A_TOT + a) * D_IN;
            #pragma unroll
            for (int p = 0; p < 5; p++) {
                int e = p * NTHR + tid;
                int row = e / 5, d = e - row * 5;
                cp_async4(smem_u32(&sm.G[1 - buf][row][d]), gp + (size_t)row * rstride + d);
            }
            CP_COMMIT();
        }

        // ---- G fragments: direct build from fp32 smem (conflict-free LDS.64) ----
        uint32_t gfh[2][2], gfl[2][2];
        {
            int rbase = wid * 32 + (lane >> 2);
            #pragma unroll
            for (int rt = 0; rt < 2; rt++)
                #pragma unroll
                for (int hh = 0; hh < 2; hh++) {
                    int row = rbase + rt * 16 + hh * 8;
                    float2 v = *(const float2*)&sm.G[buf][row][c2i];
                    split_pack_h(v.x, v.y, gfh[rt][hh], gfl[rt][hh]);
                }
        }

        // ---- layer 1: C1 = b1 + Ghi*W1hi (k8) + [Ghi|Glo]*[W1lo|W1hi] (k16) ----
        uint32_t Af[2][4][4];
        #pragma unroll
        for (int nt = 0; nt < 8; nt++) {
            float2 bb = *(const float2*)&sm.b1s[nt * 8 + c2i];
            #pragma unroll
            for (int rt = 0; rt < 2; rt++) {
                float C1[4] = {bb.x, bb.y, bb.x, bb.y};
                mma_f16_k8(C1, gfh[rt], w1h[nt]);
                uint32_t ak16[4] = {gfh[rt][0], gfh[rt][1], gfl[rt][0], gfl[rt][1]};
                uint32_t bk16[2] = {w1l[nt], w1h[nt]};
                mma_f16_k16(C1, ak16, bk16);
                // tanh.approx (1 MUFU each) -> fp16 pack
                float t0 = tanh_approx(C1[0]);
                float t1 = tanh_approx(C1[1]);
                float t2 = tanh_approx(C1[2]);
                float t3 = tanh_approx(C1[3]);
                __half2 th = __floats2half2_rn(t0, t1);
                __half2 uh = __floats2half2_rn(t2, t3);
                Af[rt][nt >> 1][(nt & 1) * 2 + 0] = *reinterpret_cast<uint32_t*>(&th);
                Af[rt][nt >> 1][(nt & 1) * 2 + 1] = *reinterpret_cast<uint32_t*>(&uh);
            }
        }

        // ---- layer 2 (single fp16 product) + fused epilogue ----
        float ee[4] = {0.f, 0.f, 0.f, 0.f};
        #pragma unroll
        for (int nh = 0; nh < 2; nh++) {
            float C[2][4][4];
            #pragma unroll
            for (int nt = 0; nt < 4; nt++) {
                float2 bb = *(const float2*)&sm.b2s[(nh * 4 + nt) * 8 + c2i];
                #pragma unroll
                for (int rt = 0; rt < 2; rt++) {
                    C[rt][nt][0] = bb.x; C[rt][nt][1] = bb.y;
                    C[rt][nt][2] = bb.x; C[rt][nt][3] = bb.y;
                }
            }
            #pragma unroll
            for (int ks = 0; ks < 4; ks++) {
                #pragma unroll
                for (int ntp = 0; ntp < 2; ntp++) {
                    int row = ks * 16 + sel_k * 8 + r_in;
                    int ntc = nh * 4 + ntp * 2 + sel_n;
                    uint32_t off = (uint32_t)row * 128 + ((uint32_t)(ntc ^ r_in) << 4);
                    uint32_t bh[4];
                    ldsm_x4t(bh, smem_u32((char*)sm.Bhi + off));
                    #pragma unroll
                    for (int ntl = 0; ntl < 2; ntl++) {
                        int nt = ntp * 2 + ntl;
                        #pragma unroll
                        for (int rt = 0; rt < 2; rt++)
                            mma_f16_k16(C[rt][nt], Af[rt][ks], &bh[ntl * 2]);
                    }
                }
            }
            #pragma unroll
            for (int nt = 0; nt < 4; nt++) {
                float2 ww = *(const float2*)&sm.w3s[(nh * 4 + nt) * 8 + c2i];
                #pragma unroll
                for (int rt = 0; rt < 2; rt++) {
                    float t0 = tanh_approx(C[rt][nt][0]);
                    float t1 = tanh_approx(C[rt][nt][1]);
                    float t2 = tanh_approx(C[rt][nt][2]);
                    float t3 = tanh_approx(C[rt][nt][3]);
                    ee[rt * 2 + 0] = fmaf(t0, ww.x, fmaf(t1, ww.y, ee[rt * 2 + 0]));
                    ee[rt * 2 + 1] = fmaf(t2, ww.x, fmaf(t3, ww.y, ee[rt * 2 + 1]));
                }
            }
        }

        // ---- reduce + store ----
        #pragma unroll
        for (int i = 0; i < 4; i++) {
            ee[i] += __shfl_xor_sync(0xFFFFFFFFu, ee[i], 1);
            ee[i] += __shfl_xor_sync(0xFFFFFFFFu, ee[i], 2);
        }
        if ((lane & 3) == 0) {
            float e3 = sm.b3s;
            int q = lane >> 2;
            int r = sBase + t * M_TILE + wid * 32 + q;
            out[(size_t)(r)      * A_TOT + a] = ee[0] + e3;
            out[(size_t)(r + 8)  * A_TOT + a] = ee[1] + e3;
            out[(size_t)(r + 16) * A_TOT + a] = ee[2] + e3;
            out[(size_t)(r + 24) * A_TOT + a] = ee[3] + e3;
        }

        // ---- wait for prefetched g, single barrier per tile ----
        if (t + 1 < TILES) {
            CP_WAIT0();
            __syncthreads();
        }
    }
}

extern "C" void kernel_launch(void* const* d_in, const int* in_sizes, int n_in,
                              void* d_out, int out_size)
{
    const float* g  = (const float*)d_in[0];
    const float* W1 = (const float*)d_in[1];
    const float* b1 = (const float*)d_in[2];
    const float* W2 = (const float*)d_in[3];
    const float* b2 = (const float*)d_in[4];
    const float* W3 = (const float*)d_in[5];
    const float* b3 = (const float*)d_in[6];
    float* out = (float*)d_out;

    mlp_kernel<<<dim3(S_TOT / SPT, A_TOT), NTHR>>>(g, W1, b1, W2, b2, W3, b3, out);
}

// round 15
// speedup vs baseline: 1.4557x; 1.0281x over previous
#include <cuda_runtime.h>
#include <cuda_fp16.h>
#include <cstdint>

#define S_TOT  4096
#define A_TOT  1024
#define D_IN   5
#define H      64
#define M_TILE 128
#define NTHR   128
#define TILES  8
#define SPT    (M_TILE * TILES)   // structs per CTA

// ---------------- helpers ----------------
__device__ __forceinline__ uint32_t smem_u32(const void* p) {
    uint32_t a;
    asm("{ .reg .u64 t; cvta.to.shared.u64 t, %1; cvt.u32.u64 %0, t; }" : "=r"(a) : "l"(p));
    return a;
}
__device__ __forceinline__ float tanh_approx(float x) {
    float y; asm("tanh.approx.f32 %0, %1;" : "=f"(y) : "f"(x)); return y;
}
__device__ __forceinline__ uint32_t tanh_h2(uint32_t x) {
    uint32_t y; asm("tanh.approx.f16x2 %0, %1;" : "=r"(y) : "r"(x)); return y;
}
__device__ __forceinline__ void split_pack_h(float x, float y, uint32_t& hi, uint32_t& lo) {
    __half2 h2 = __floats2half2_rn(x, y);
    float hx = __low2float(h2), hy = __high2float(h2);
    __half2 l2 = __floats2half2_rn(x - hx, y - hy);
    hi = *reinterpret_cast<uint32_t*>(&h2);
    lo = *reinterpret_cast<uint32_t*>(&l2);
}
__device__ __forceinline__ uint32_t pack_h2(float x, float y) {
    __half2 h2 = __floats2half2_rn(x, y);
    return *reinterpret_cast<uint32_t*>(&h2);
}
__device__ __forceinline__ void ldsm_x4t(uint32_t* r, uint32_t addr) {
    asm volatile("ldmatrix.sync.aligned.m8n8.x4.trans.shared.b16 {%0,%1,%2,%3}, [%4];"
                 : "=r"(r[0]), "=r"(r[1]), "=r"(r[2]), "=r"(r[3]) : "r"(addr));
}
__device__ __forceinline__ void mma_f16_k16(float* c, const uint32_t* a, const uint32_t* b) {
    asm volatile("mma.sync.aligned.m16n8k16.row.col.f32.f16.f16.f32 "
                 "{%0,%1,%2,%3}, {%4,%5,%6,%7}, {%8,%9}, {%0,%1,%2,%3};"
                 : "+f"(c[0]), "+f"(c[1]), "+f"(c[2]), "+f"(c[3])
                 : "r"(a[0]), "r"(a[1]), "r"(a[2]), "r"(a[3]), "r"(b[0]), "r"(b[1]));
}
__device__ __forceinline__ void cp_async4(uint32_t dst, const float* src) {
    asm volatile("cp.async.ca.shared.global [%0], [%1], 4;" :: "r"(dst), "l"(src));
}
#define CP_COMMIT() asm volatile("cp.async.commit_group;" ::: "memory")
#define CP_WAIT0()  asm volatile("cp.async.wait_group 0;" ::: "memory")

// Static smem (~19.5 KB). B tile: rows 128B, 16B chunks XOR-swizzled (chunk ^= row&7).
struct SmemT {
    __align__(128) __half Bhi[H * H];          // 8 KB  W2 fp16 [k][n]
    __align__(16)  float  G[2][M_TILE][8];     // 8 KB  g fp32, k padded 5->8, dbl-buffer
    __align__(16)  float  W1s[H][8];           // 2 KB  W1 fp32 [n][k], k padded
    float b1s[H], b2s[H], w3s[H], b3s;
};

__global__ __launch_bounds__(NTHR, 5) void mlp_kernel(
    const float* __restrict__ g,  const float* __restrict__ W1, const float* __restrict__ b1,
    const float* __restrict__ W2, const float* __restrict__ b2,
    const float* __restrict__ W3, const float* __restrict__ b3, float* __restrict__ out)
{
    __shared__ SmemT sm;
    const int tid  = threadIdx.x;
    const int wid  = tid >> 5;
    const int lane = tid & 31;
    const int a    = blockIdx.y;
    const int sBase = blockIdx.x * SPT;
    const size_t rstride = (size_t)A_TOT * D_IN;

    // zero G pads (cols 5..7) once; cp.async never touches them
    sm.G[0][tid][5] = 0.f; sm.G[0][tid][6] = 0.f; sm.G[0][tid][7] = 0.f;
    sm.G[1][tid][5] = 0.f; sm.G[1][tid][6] = 0.f; sm.G[1][tid][7] = 0.f;

    // ---- kick off async g load for tile 0 ----
    {
        const float* gp = g + ((size_t)sBase * A_TOT + a) * D_IN;
        #pragma unroll
        for (int p = 0; p < 5; p++) {
            int e = p * NTHR + tid;
            int row = e / 5, d = e - row * 5;
            cp_async4(smem_u32(&sm.G[0][row][d]), gp + (size_t)row * rstride + d);
        }
        CP_COMMIT();
    }

    // ---- once-per-CTA staging ----
    if (tid < H) {
        sm.b1s[tid] = b1[(size_t)a * H + tid];
        sm.b2s[tid] = b2[(size_t)a * H + tid];
        sm.w3s[tid] = W3[(size_t)a * H + tid];
    }
    if (tid == 0) sm.b3s = b3[a];

    {   // W2 -> Bhi (single fp16), swizzled
        const float* W2a = W2 + (size_t)a * H * H;
        #pragma unroll
        for (int it = 0; it < 4; it++) {
            int ch = tid + it * NTHR;
            int k = ch >> 3, nc = ch & 7;
            const float4* src = (const float4*)(W2a + k * H + nc * 8);
            float4 w0 = src[0], w1 = src[1];
            uint32_t off = (uint32_t)k * 128 + ((uint32_t)(nc ^ (k & 7)) << 4);
            *(uint4*)((char*)sm.Bhi + off) = make_uint4(
                pack_h2(w0.x, w0.y), pack_h2(w0.z, w0.w),
                pack_h2(w1.x, w1.y), pack_h2(w1.z, w1.w));
        }
    }
    {   // W1 fp32 transposed [n][k], k padded with zeros
        const float* W1a = W1 + (size_t)a * D_IN * H;
        #pragma unroll
        for (int it = 0; it < 4; it++) {
            int e = it * NTHR + tid;                     // e = n*8 + k
            int n = e >> 3, k = e & 7;
            sm.W1s[n][k] = (k < D_IN) ? W1a[k * H + n] : 0.0f;
        }
    }
    CP_WAIT0();
    __syncthreads();

    // ---- W1 fragments: hi/lo split, built once, held in regs ----
    uint32_t w1h[8], w1l[8];
    {
        int q = lane >> 2, k0 = (lane & 3) * 2;
        #pragma unroll
        for (int nt = 0; nt < 8; nt++) {
            float2 v = *(const float2*)&sm.W1s[nt * 8 + q][k0];
            split_pack_h(v.x, v.y, w1h[nt], w1l[nt]);
        }
    }

    const int c2i = (lane & 3) * 2;
    // x4t lane addressing (lane-consts)
    const int r_in  = lane & 7;
    const int sel_k = (lane >> 3) & 1;
    const int sel_n = lane >> 4;

    for (int t = 0; t < TILES; t++) {
        const int buf = t & 1;

        // ---- async prefetch of next g tile ----
        if (t + 1 < TILES) {
            const float* gp = g + ((size_t)(sBase + (t + 1) * M_TILE) * A_TOT + a) * D_IN;
            #pragma unroll
            for (int p = 0; p < 5; p++) {
                int e = p * NTHR + tid;
                int row = e / 5, d = e - row * 5;
                cp_async4(smem_u32(&sm.G[1 - buf][row][d]), gp + (size_t)row * rstride + d);
            }
            CP_COMMIT();
        }

        // ---- G fragments (hi only): direct build from fp32 smem ----
        uint32_t gfh[2][2];
        {
            int rbase = wid * 32 + (lane >> 2);
            #pragma unroll
            for (int rt = 0; rt < 2; rt++)
                #pragma unroll
                for (int hh = 0; hh < 2; hh++) {
                    int row = rbase + rt * 16 + hh * 8;
                    float2 v = *(const float2*)&sm.G[buf][row][c2i];
                    gfh[rt][hh] = pack_h2(v.x, v.y);
                }
        }

        // ---- layer 1: ONE k16 MMA per (nt,rt): Ghi*(W1hi + W1lo), f16x2 tanh ----
        uint32_t Af[2][4][4];
        #pragma unroll
        for (int nt = 0; nt < 8; nt++) {
            float2 bb = *(const float2*)&sm.b1s[nt * 8 + c2i];
            uint32_t bk16[2] = {w1h[nt], w1l[nt]};
            #pragma unroll
            for (int rt = 0; rt < 2; rt++) {
                float C1[4] = {bb.x, bb.y, bb.x, bb.y};
                uint32_t ak16[4] = {gfh[rt][0], gfh[rt][1], gfh[rt][0], gfh[rt][1]};
                mma_f16_k16(C1, ak16, bk16);
                Af[rt][nt >> 1][(nt & 1) * 2 + 0] = tanh_h2(pack_h2(C1[0], C1[1]));
                Af[rt][nt >> 1][(nt & 1) * 2 + 1] = tanh_h2(pack_h2(C1[2], C1[3]));
            }
        }

        // ---- layer 2 (single fp16 product) + fused epilogue ----
        float ee[4] = {0.f, 0.f, 0.f, 0.f};
        #pragma unroll
        for (int nh = 0; nh < 2; nh++) {
            float C[2][4][4];
            #pragma unroll
            for (int nt = 0; nt < 4; nt++) {
                float2 bb = *(const float2*)&sm.b2s[(nh * 4 + nt) * 8 + c2i];
                #pragma unroll
                for (int rt = 0; rt < 2; rt++) {
                    C[rt][nt][0] = bb.x; C[rt][nt][1] = bb.y;
                    C[rt][nt][2] = bb.x; C[rt][nt][3] = bb.y;
                }
            }
            #pragma unroll
            for (int ks = 0; ks < 4; ks++) {
                #pragma unroll
                for (int ntp = 0; ntp < 2; ntp++) {
                    int row = ks * 16 + sel_k * 8 + r_in;
                    int ntc = nh * 4 + ntp * 2 + sel_n;
                    uint32_t off = (uint32_t)row * 128 + ((uint32_t)(ntc ^ r_in) << 4);
                    uint32_t bh[4];
                    ldsm_x4t(bh, smem_u32((char*)sm.Bhi + off));
                    #pragma unroll
                    for (int ntl = 0; ntl < 2; ntl++) {
                        int nt = ntp * 2 + ntl;
                        #pragma unroll
                        for (int rt = 0; rt < 2; rt++)
                            mma_f16_k16(C[rt][nt], Af[rt][ks], &bh[ntl * 2]);
                    }
                }
            }
            #pragma unroll
            for (int nt = 0; nt < 4; nt++) {
                float2 ww = *(const float2*)&sm.w3s[(nh * 4 + nt) * 8 + c2i];
                #pragma unroll
                for (int rt = 0; rt < 2; rt++) {
                    float t0 = tanh_approx(C[rt][nt][0]);
                    float t1 = tanh_approx(C[rt][nt][1]);
                    float t2 = tanh_approx(C[rt][nt][2]);
                    float t3 = tanh_approx(C[rt][nt][3]);
                    ee[rt * 2 + 0] = fmaf(t0, ww.x, fmaf(t1, ww.y, ee[rt * 2 + 0]));
                    ee[rt * 2 + 1] = fmaf(t2, ww.x, fmaf(t3, ww.y, ee[rt * 2 + 1]));
                }
            }
        }

        // ---- reduce + store ----
        #pragma unroll
        for (int i = 0; i < 4; i++) {
            ee[i] += __shfl_xor_sync(0xFFFFFFFFu, ee[i], 1);
            ee[i] += __shfl_xor_sync(0xFFFFFFFFu, ee[i], 2);
        }
        if ((lane & 3) == 0) {
            float e3 = sm.b3s;
            int q = lane >> 2;
            int r = sBase + t * M_TILE + wid * 32 + q;
            out[(size_t)(r)      * A_TOT + a] = ee[0] + e3;
            out[(size_t)(r + 8)  * A_TOT + a] = ee[1] + e3;
            out[(size_t)(r + 16) * A_TOT + a] = ee[2] + e3;
            out[(size_t)(r + 24) * A_TOT + a] = ee[3] + e3;
        }

        // ---- wait for prefetched g, single barrier per tile ----
        if (t + 1 < TILES) {
            CP_WAIT0();
            __syncthreads();
        }
    }
}

extern "C" void kernel_launch(void* const* d_in, const int* in_sizes, int n_in,
                              void* d_out, int out_size)
{
    const float* g  = (const float*)d_in[0];
    const float* W1 = (const float*)d_in[1];
    const float* b1 = (const float*)d_in[2];
    const float* W2 = (const float*)d_in[3];
    const float* b2 = (const float*)d_in[4];
    const float* W3 = (const float*)d_in[5];
    const float* b3 = (const float*)d_in[6];
    float* out = (float*)d_out;

    mlp_kernel<<<dim3(S_TOT / SPT, A_TOT), NTHR>>>(g, W1, b1, W2, b2, W3, b3, out);
}